// round 7
// baseline (speedup 1.0000x reference)
#include <cuda_runtime.h>
#include <math.h>
#include <stdint.h>

#define BB 2
#define SS 2048
#define EE 512
#define NHH 8
#define DHH 64
#define BH (BB*NHH)
#define NCHUNK (SS/64)    // 32 chunks of 64

typedef unsigned long long ull;

// Scratch (device globals: allocation-free)
__device__ float g_ig[BH*SS];
__device__ float g_fg[BH*SS];
__device__ float g_u [BH*SS];      // ig_j - cs_j
__device__ float g_M [BH*SS];      // prefix max of u
__device__ float g_m [BH*SS];      // cs_i + M_i (= max_log_D row max)
__device__ float g_w [BH*SS];      // exp(u_j - cmax_of_chunk)
__device__ float g_cmax[BH*NCHUNK];

// ---- packed f32x2 helpers (Blackwell) ----
__device__ __forceinline__ ull fma2(ull a, ull b, ull c) {
    ull d;
    asm("fma.rn.f32x2 %0, %1, %2, %3;" : "=l"(d) : "l"(a), "l"(b), "l"(c));
    return d;
}
__device__ __forceinline__ ull add2(ull a, ull b) {
    ull d;
    asm("add.rn.f32x2 %0, %1, %2;" : "=l"(d) : "l"(a), "l"(b));
    return d;
}
__device__ __forceinline__ ull pack2(float a, float b) {
    ull r;
    asm("mov.b64 %0, {%1, %2};" : "=l"(r) : "f"(a), "f"(b));
    return r;
}
__device__ __forceinline__ float2 unpack2(ull v) {
    float2 r;
    asm("mov.b64 {%0, %1}, %2;" : "=f"(r.x), "=f"(r.y) : "l"(v));
    return r;
}
__device__ __forceinline__ uint32_t s2u(const void* p) {
    uint32_t a;
    asm("{ .reg .u64 t; cvta.to.shared.u64 t, %1; cvt.u32.u64 %0, t; }"
        : "=r"(a) : "l"(p));
    return a;
}
__device__ __forceinline__ void cp16(uint32_t d, const void* s) {
    asm volatile("cp.async.cg.shared.global [%0], [%1], 16;" :: "r"(d), "l"(s));
}
#define CP_COMMIT() asm volatile("cp.async.commit_group;")
template<int N> __device__ __forceinline__ void cp_wait() {
    asm volatile("cp.async.wait_group %0;" :: "n"(N));
}

// ---------------------------------------------------------------------------
// Kernel 1: gate projections. Loop-interchanged so W needs 1 live register:
// outer k-step, inner 8-row accumulate. ~30 regs -> 4 blocks/SM.
// grid = B*S/8 blocks, 512 threads (warp w -> head (w&7), gate (w>>3))
// ---------------------------------------------------------------------------
__global__ void __launch_bounds__(512)
gates_kernel(const float* __restrict__ q,
             const float* __restrict__ k,
             const float* __restrict__ v,
             const float* __restrict__ Wi,
             const float* __restrict__ bi,
             const float* __restrict__ Wf,
             const float* __restrict__ bf) {
    __shared__ float gin[8 * 1536];   // 48 KB
    const int tid = threadIdx.x;
    const int r0  = blockIdx.x * 8;

    const float4* q4 = (const float4*)q;
    const float4* k4 = (const float4*)k;
    const float4* v4 = (const float4*)v;
    float4* gin4 = (float4*)gin;
    for (int idx = tid; idx < 8 * 384; idx += 512) {
        int row = idx / 384;
        int c4  = idx - row * 384;
        int r   = r0 + row;
        float4 val;
        if (c4 < 128)       val = q4[r * 128 + c4];
        else if (c4 < 256)  val = k4[r * 128 + (c4 - 128)];
        else                val = v4[r * 128 + (c4 - 256)];
        gin4[row * 384 + c4] = val;
    }
    __syncthreads();

    const int wid  = tid >> 5;
    const int lane = tid & 31;
    const int n    = wid & 7;
    const int isF  = wid >> 3;
    const float* W  = (isF ? Wf : Wi) + n * 1536 + lane;
    const float* g0 = gin + lane;
    const float bias = isF ? bf[n] : bi[n];

    float acc[8] = {0.f, 0.f, 0.f, 0.f, 0.f, 0.f, 0.f, 0.f};
    for (int t = 0; t < 48; t++) {
        float wv = W[t * 32];
        const float* gp = g0 + t * 32;
        #pragma unroll
        for (int r = 0; r < 8; r++) acc[r] += gp[r * 1536] * wv;
    }

    float* dst = isF ? g_fg : g_ig;
    #pragma unroll
    for (int r = 0; r < 8; r++) {
        float a = acc[r];
        #pragma unroll
        for (int o = 16; o > 0; o >>= 1) a += __shfl_xor_sync(0xffffffffu, a, o);
        if (lane == 0) {
            int rr = r0 + r;
            int b = rr / SS, sIdx = rr - b * SS;
            dst[(b * NHH + n) * SS + sIdx] = a + bias;
        }
    }
}

// ---------------------------------------------------------------------------
// Kernel 2: per-(b,n) scan. cs=cumsum(logsig(fg)); u=ig-cs; M=prefmax(u);
// m=cs+M; per-64-chunk max (g_cmax); g_w = exp(u - cmax).
// grid = BH blocks, 256 threads, 8 elems/thread (chunk = 8 threads).
// ---------------------------------------------------------------------------
__global__ void scan_kernel() {
    __shared__ float sh[256];
    const int bh   = blockIdx.x;
    const int tid  = threadIdx.x;
    const int base = bh * SS + tid * 8;

    float csl[8];
    float run = 0.f;
    #pragma unroll
    for (int t = 0; t < 8; t++) {
        float x  = g_fg[base + t];
        float ls = fminf(x, 0.f) - log1pf(expf(-fabsf(x)));  // log_sigmoid
        run += ls;
        csl[t] = run;
    }
    sh[tid] = run;
    __syncthreads();
    #pragma unroll
    for (int off = 1; off < 256; off <<= 1) {
        float vv = (tid >= off) ? sh[tid - off] : 0.f;
        __syncthreads();
        sh[tid] += vv;
        __syncthreads();
    }
    float offs = (tid > 0) ? sh[tid - 1] : 0.f;

    float u[8], pm[8];
    float runm = -INFINITY;
    #pragma unroll
    for (int t = 0; t < 8; t++) {
        float cs = offs + csl[t];
        csl[t] = cs;
        float ut = g_ig[base + t] - cs;
        u[t] = ut;
        runm = fmaxf(runm, ut);
        pm[t] = runm;
    }
    float cm = runm;
    cm = fmaxf(cm, __shfl_xor_sync(0xffffffffu, cm, 1));
    cm = fmaxf(cm, __shfl_xor_sync(0xffffffffu, cm, 2));
    cm = fmaxf(cm, __shfl_xor_sync(0xffffffffu, cm, 4));
    if ((tid & 7) == 0) g_cmax[bh * NCHUNK + (tid >> 3)] = cm;

    __syncthreads();
    sh[tid] = runm;
    __syncthreads();
    #pragma unroll
    for (int off = 1; off < 256; off <<= 1) {
        float vv = (tid >= off) ? sh[tid - off] : -INFINITY;
        __syncthreads();
        sh[tid] = fmaxf(sh[tid], vv);
        __syncthreads();
    }
    float moffs = (tid > 0) ? sh[tid - 1] : -INFINITY;
    #pragma unroll
    for (int t = 0; t < 8; t++) {
        float Mi = fmaxf(moffs, pm[t]);
        g_u[base + t] = u[t];
        g_M[base + t] = Mi;
        g_m[base + t] = csl[t] + Mi;
        g_w[base + t] = __expf(u[t] - cm);
    }
}

// ---------------------------------------------------------------------------
// Kernel 3: causal decayed attention. 2 threads per query row (adjacent
// lanes, DH halves): half the regs, 16 warps/SM. cp.async double-buffering,
// exp hoisted, chunk truncation via one ballot. grid = (S/128, BH), 256 thr.
// ---------------------------------------------------------------------------
#define ATTN_SMEM_BYTES (16640 * 4)

__global__ void __launch_bounds__(256)
attn_kernel(const float* __restrict__ q,
            const float* __restrict__ k,
            const float* __restrict__ v,
            float* __restrict__ out) {
    extern __shared__ float dynsh[];
    float* ksh  = dynsh;              // [2][4096]
    float* vsh  = dynsh + 8192;       // [2][4096]
    float* wshp = dynsh + 16384;      // [2][64]
    float* ushp = dynsh + 16512;      // [2][64]
    __shared__ int s_cstart;

    const int bh   = blockIdx.y;
    const int b    = bh >> 3;
    const int n    = bh & 7;
    const int ti   = (int)gridDim.x - 1 - (int)blockIdx.x;
    const int tid  = threadIdx.x;
    const int row  = tid >> 1;               // 0..127
    const int half = tid & 1;                // DH half
    const int i    = ti * 128 + row;

    const uint32_t kb = s2u(ksh);
    const uint32_t vb = kb + 32768u;
    const uint32_t wb = kb + 65536u;
    const uint32_t ub = kb + 66048u;

    // q half-row in packed registers (16 x f32x2 = 32 floats)
    ull qv2[16];
    const float4* qp = (const float4*)q + (b * SS + i) * 128 + n * 16 + half * 8;
    #pragma unroll
    for (int t = 0; t < 8; t++) {
        float4 val = qp[t];
        qv2[2*t]   = pack2(val.x, val.y);
        qv2[2*t+1] = pack2(val.z, val.w);
    }

    const float Mi  = g_M[bh * SS + i];
    const int cdiag = i >> 6;
    const int c_end = 2 * ti + 2;

    // truncation start via one parallel ballot (warp 0)
    const float thr = g_M[bh * SS + ti * 128] - 88.0f;
    if (tid < 32) {
        float cmv = g_cmax[bh * NCHUNK + tid];
        bool liveb = (cmv > thr) && (tid < c_end);
        unsigned msk = __ballot_sync(0xffffffffu, liveb);
        if (tid == 0) {
            int first = msk ? (__ffs(msk) - 1) : (2 * ti);
            s_cstart = (first < 2 * ti) ? first : (2 * ti);
        }
    }
    __syncthreads();
    const int c_start = s_cstart;

#define STAGE(cc, bufidx) do {                                               \
    int j0_ = (cc) * 64;                                                     \
    const float* kp_ = k + (size_t)(b * SS + j0_) * EE + n * 64;             \
    const float* vp_ = v + (size_t)(b * SS + j0_) * EE + n * 64;             \
    _Pragma("unroll")                                                        \
    for (int r_ = 0; r_ < 4; r_++) {                                         \
        int l_ = tid + 256 * r_; int row_ = l_ >> 4, c4_ = l_ & 15;          \
        cp16(kb + (bufidx) * 16384u + (uint32_t)l_ * 16u, kp_ + row_ * EE + c4_ * 4); \
        cp16(vb + (bufidx) * 16384u + (uint32_t)l_ * 16u, vp_ + row_ * EE + c4_ * 4); \
    }                                                                        \
    if (tid < 16)                                                            \
        cp16(wb + (bufidx) * 256u + (uint32_t)tid * 16u, g_w + bh * SS + j0_ + tid * 4); \
    else if (tid < 32)                                                       \
        cp16(ub + (bufidx) * 256u + (uint32_t)(tid - 16) * 16u, g_u + bh * SS + j0_ + (tid - 16) * 4); \
} while (0)

    ull acc2[16];
    #pragma unroll
    for (int t = 0; t < 16; t++) acc2[t] = 0ull;
    float ssum = 0.f;

    STAGE(c_start, 0);
    CP_COMMIT();

    for (int c = c_start; c < c_end; c++) {
        const int cur = (c - c_start) & 1;
        __syncthreads();
        if (c + 1 < c_end) STAGE(c + 1, cur ^ 1);
        CP_COMMIT();
        cp_wait<1>();
        __syncthreads();

        const float* kbase = ksh + cur * 4096 + half * 32;
        const float* vbase = vsh + cur * 4096 + half * 32;

        if (c < cdiag) {
            const float es = __expf(g_cmax[bh * NCHUNK + c] - Mi);  // <= 1
            // warp-uniform skip; dead rows just compute zeros
            if (__any_sync(0xffffffffu, es > 0.f)) {
                const float qs = 0.125f * es;
                #pragma unroll 2
                for (int jj = 0; jj < 64; jj++) {
                    const ull* kr = (const ull*)(kbase + jj * 64);
                    ull d0 = 0ull, d1 = 0ull, d2 = 0ull, d3 = 0ull;
                    #pragma unroll
                    for (int t = 0; t < 4; t++) {
                        d0 = fma2(qv2[4*t],   kr[4*t],   d0);
                        d1 = fma2(qv2[4*t+1], kr[4*t+1], d1);
                        d2 = fma2(qv2[4*t+2], kr[4*t+2], d2);
                        d3 = fma2(qv2[4*t+3], kr[4*t+3], d3);
                    }
                    float2 s = unpack2(add2(add2(d0, d1), add2(d2, d3)));
                    float sh_ = s.x + s.y;
                    float full = sh_ + __shfl_xor_sync(0xffffffffu, sh_, 1);
                    float Cv = (full * qs) * wshp[cur * 64 + jj];
                    ssum += Cv;
                    ull cv2 = pack2(Cv, Cv);
                    const ull* vr = (const ull*)(vbase + jj * 64);
                    #pragma unroll
                    for (int t = 0; t < 16; t++)
                        acc2[t] = fma2(cv2, vr[t], acc2[t]);
                }
            }
        } else if (c == cdiag) {
            const int j0 = c * 64;
            #pragma unroll 2
            for (int jj = 0; jj < 64; jj++) {
                const ull* kr = (const ull*)(kbase + jj * 64);
                ull d0 = 0ull, d1 = 0ull, d2 = 0ull, d3 = 0ull;
                #pragma unroll
                for (int t = 0; t < 4; t++) {
                    d0 = fma2(qv2[4*t],   kr[4*t],   d0);
                    d1 = fma2(qv2[4*t+1], kr[4*t+1], d1);
                    d2 = fma2(qv2[4*t+2], kr[4*t+2], d2);
                    d3 = fma2(qv2[4*t+3], kr[4*t+3], d3);
                }
                float2 s = unpack2(add2(add2(d0, d1), add2(d2, d3)));
                float sh_ = s.x + s.y;
                float full = sh_ + __shfl_xor_sync(0xffffffffu, sh_, 1);
                float qk = full * 0.125f;
                float wq = __expf(ushp[cur * 64 + jj] - Mi);
                float Cv = (j0 + jj <= i) ? qk * wq : 0.f;
                ssum += Cv;
                ull cv2 = pack2(Cv, Cv);
                const ull* vr = (const ull*)(vbase + jj * 64);
                #pragma unroll
                for (int t = 0; t < 16; t++)
                    acc2[t] = fma2(cv2, vr[t], acc2[t]);
            }
        }
        // c > cdiag: nothing (fully future chunk for this row)
    }
#undef STAGE

    // unpack accumulators (this thread's 32 of 64 dims)
    float accf[32];
    #pragma unroll
    for (int t = 0; t < 16; t++) {
        float2 p = unpack2(acc2[t]);
        accf[2*t]   = p.x;
        accf[2*t+1] = p.y;
    }

    // normalizer (identical on both halves): max(|sum C|, exp(-m)) + eps
    const float mi   = g_m[bh * SS + i];
    const float norm = fmaxf(fabsf(ssum), __expf(-mi)) + 1e-6f;
    const float inv  = 1.0f / norm;

    // LayerNorm over full DH via pair reduction
    float sum_h = 0.f;
    #pragma unroll
    for (int t = 0; t < 32; t++) sum_h += accf[t];
    float sum = sum_h + __shfl_xor_sync(0xffffffffu, sum_h, 1);
    const float mu = sum * inv * (1.0f / 64.0f);

    float var_h = 0.f;
    #pragma unroll
    for (int t = 0; t < 32; t++) {
        float dx = accf[t] * inv - mu;
        var_h += dx * dx;
    }
    float var = (var_h + __shfl_xor_sync(0xffffffffu, var_h, 1)) * (1.0f / 64.0f);
    const float sc = rsqrtf(var + 1e-5f);

    float4* o4 = (float4*)out + (bh * SS + i) * 16 + half * 8;
    #pragma unroll
    for (int t = 0; t < 8; t++) {
        o4[t] = make_float4((accf[4*t]   * inv - mu) * sc,
                            (accf[4*t+1] * inv - mu) * sc,
                            (accf[4*t+2] * inv - mu) * sc,
                            (accf[4*t+3] * inv - mu) * sc);
    }
}

// ---------------------------------------------------------------------------
extern "C" void kernel_launch(void* const* d_in, const int* in_sizes, int n_in,
                              void* d_out, int out_size) {
    const float* q  = (const float*)d_in[0];
    const float* k  = (const float*)d_in[1];
    const float* v  = (const float*)d_in[2];
    const float* Wi = (const float*)d_in[3];
    const float* bi = (const float*)d_in[4];
    const float* Wf = (const float*)d_in[5];
    const float* bf = (const float*)d_in[6];
    float* out = (float*)d_out;

    cudaFuncSetAttribute(attn_kernel,
                         cudaFuncAttributeMaxDynamicSharedMemorySize,
                         ATTN_SMEM_BYTES);

    gates_kernel<<<(BB * SS) / 8, 512>>>(q, k, v, Wi, bi, Wf, bf);
    scan_kernel<<<BH, 256>>>();
    attn_kernel<<<dim3(SS / 128, BH), 256, ATTN_SMEM_BYTES>>>(q, k, v, out);
}

// round 8
// speedup vs baseline: 1.2489x; 1.2489x over previous
#include <cuda_runtime.h>
#include <math.h>
#include <stdint.h>

#define BB 2
#define SS 2048
#define EE 512
#define NHH 8
#define DHH 64
#define BH (BB*NHH)
#define NCHUNK (SS/64)    // 32 chunks of 64

typedef unsigned long long ull;

// Scratch (device globals: allocation-free)
__device__ float g_ig[BH*SS];
__device__ float g_fg[BH*SS];
__device__ float g_u [BH*SS];      // ig_j - cs_j
__device__ float g_M [BH*SS];      // prefix max of u
__device__ float g_m [BH*SS];      // cs_i + M_i (= max_log_D row max)
__device__ float g_w [BH*SS];      // exp(u_j - cmax_of_chunk)
__device__ float g_cmax[BH*NCHUNK];

// ---- packed f32x2 helpers (Blackwell) ----
__device__ __forceinline__ ull fma2(ull a, ull b, ull c) {
    ull d;
    asm("fma.rn.f32x2 %0, %1, %2, %3;" : "=l"(d) : "l"(a), "l"(b), "l"(c));
    return d;
}
__device__ __forceinline__ ull add2(ull a, ull b) {
    ull d;
    asm("add.rn.f32x2 %0, %1, %2;" : "=l"(d) : "l"(a), "l"(b));
    return d;
}
__device__ __forceinline__ ull pack2(float a, float b) {
    ull r;
    asm("mov.b64 %0, {%1, %2};" : "=l"(r) : "f"(a), "f"(b));
    return r;
}
__device__ __forceinline__ float2 unpack2(ull v) {
    float2 r;
    asm("mov.b64 {%0, %1}, %2;" : "=f"(r.x), "=f"(r.y) : "l"(v));
    return r;
}
__device__ __forceinline__ uint32_t s2u(const void* p) {
    uint32_t a;
    asm("{ .reg .u64 t; cvta.to.shared.u64 t, %1; cvt.u32.u64 %0, t; }"
        : "=r"(a) : "l"(p));
    return a;
}
__device__ __forceinline__ void cp16(uint32_t d, const void* s) {
    asm volatile("cp.async.cg.shared.global [%0], [%1], 16;" :: "r"(d), "l"(s));
}
#define CP_COMMIT() asm volatile("cp.async.commit_group;")
template<int N> __device__ __forceinline__ void cp_wait() {
    asm volatile("cp.async.wait_group %0;" :: "n"(N));
}

// float4 <-> 2x f32x2 reinterpret (free: float4 = 4 consecutive regs)
union F4U2 { float4 f4; ull u2[2]; };

// ---------------------------------------------------------------------------
// Kernel 1: gate projections (R7 version: 1 live W register, 31 regs total).
// grid = B*S/8 blocks, 512 threads (warp w -> head (w&7), gate (w>>3))
// ---------------------------------------------------------------------------
__global__ void __launch_bounds__(512)
gates_kernel(const float* __restrict__ q,
             const float* __restrict__ k,
             const float* __restrict__ v,
             const float* __restrict__ Wi,
             const float* __restrict__ bi,
             const float* __restrict__ Wf,
             const float* __restrict__ bf) {
    __shared__ float gin[8 * 1536];   // 48 KB
    const int tid = threadIdx.x;
    const int r0  = blockIdx.x * 8;

    const float4* q4 = (const float4*)q;
    const float4* k4 = (const float4*)k;
    const float4* v4 = (const float4*)v;
    float4* gin4 = (float4*)gin;
    for (int idx = tid; idx < 8 * 384; idx += 512) {
        int row = idx / 384;
        int c4  = idx - row * 384;
        int r   = r0 + row;
        float4 val;
        if (c4 < 128)       val = q4[r * 128 + c4];
        else if (c4 < 256)  val = k4[r * 128 + (c4 - 128)];
        else                val = v4[r * 128 + (c4 - 256)];
        gin4[row * 384 + c4] = val;
    }
    __syncthreads();

    const int wid  = tid >> 5;
    const int lane = tid & 31;
    const int n    = wid & 7;
    const int isF  = wid >> 3;
    const float* W  = (isF ? Wf : Wi) + n * 1536 + lane;
    const float* g0 = gin + lane;
    const float bias = isF ? bf[n] : bi[n];

    float acc[8] = {0.f, 0.f, 0.f, 0.f, 0.f, 0.f, 0.f, 0.f};
    for (int t = 0; t < 48; t++) {
        float wv = W[t * 32];
        const float* gp = g0 + t * 32;
        #pragma unroll
        for (int r = 0; r < 8; r++) acc[r] += gp[r * 1536] * wv;
    }

    float* dst = isF ? g_fg : g_ig;
    #pragma unroll
    for (int r = 0; r < 8; r++) {
        float a = acc[r];
        #pragma unroll
        for (int o = 16; o > 0; o >>= 1) a += __shfl_xor_sync(0xffffffffu, a, o);
        if (lane == 0) {
            int rr = r0 + r;
            int b = rr / SS, sIdx = rr - b * SS;
            dst[(b * NHH + n) * SS + sIdx] = a + bias;
        }
    }
}

// ---------------------------------------------------------------------------
// Kernel 2: per-(b,n) scan (unchanged).
// ---------------------------------------------------------------------------
__global__ void scan_kernel() {
    __shared__ float sh[256];
    const int bh   = blockIdx.x;
    const int tid  = threadIdx.x;
    const int base = bh * SS + tid * 8;

    float csl[8];
    float run = 0.f;
    #pragma unroll
    for (int t = 0; t < 8; t++) {
        float x  = g_fg[base + t];
        float ls = fminf(x, 0.f) - log1pf(expf(-fabsf(x)));  // log_sigmoid
        run += ls;
        csl[t] = run;
    }
    sh[tid] = run;
    __syncthreads();
    #pragma unroll
    for (int off = 1; off < 256; off <<= 1) {
        float vv = (tid >= off) ? sh[tid - off] : 0.f;
        __syncthreads();
        sh[tid] += vv;
        __syncthreads();
    }
    float offs = (tid > 0) ? sh[tid - 1] : 0.f;

    float u[8], pm[8];
    float runm = -INFINITY;
    #pragma unroll
    for (int t = 0; t < 8; t++) {
        float cs = offs + csl[t];
        csl[t] = cs;
        float ut = g_ig[base + t] - cs;
        u[t] = ut;
        runm = fmaxf(runm, ut);
        pm[t] = runm;
    }
    float cm = runm;
    cm = fmaxf(cm, __shfl_xor_sync(0xffffffffu, cm, 1));
    cm = fmaxf(cm, __shfl_xor_sync(0xffffffffu, cm, 2));
    cm = fmaxf(cm, __shfl_xor_sync(0xffffffffu, cm, 4));
    if ((tid & 7) == 0) g_cmax[bh * NCHUNK + (tid >> 3)] = cm;

    __syncthreads();
    sh[tid] = runm;
    __syncthreads();
    #pragma unroll
    for (int off = 1; off < 256; off <<= 1) {
        float vv = (tid >= off) ? sh[tid - off] : -INFINITY;
        __syncthreads();
        sh[tid] = fmaxf(sh[tid], vv);
        __syncthreads();
    }
    float moffs = (tid > 0) ? sh[tid - 1] : -INFINITY;
    #pragma unroll
    for (int t = 0; t < 8; t++) {
        float Mi = fmaxf(moffs, pm[t]);
        g_u[base + t] = u[t];
        g_M[base + t] = Mi;
        g_m[base + t] = csl[t] + Mi;
        g_w[base + t] = __expf(u[t] - cm);
    }
}

// ---------------------------------------------------------------------------
// Kernel 3: causal decayed attention. R6 skeleton (1 thread/row, 128/block),
// with: float4 shared reads (32 LDS.128/jj instead of 64 LDS.64), smem-cached
// cmax (no per-chunk LDG), ballot c_start. cp.async double-buffer.
// ---------------------------------------------------------------------------
#define ATTN_SMEM_BYTES (16640 * 4)

__global__ void __launch_bounds__(128)
attn_kernel(const float* __restrict__ q,
            const float* __restrict__ k,
            const float* __restrict__ v,
            float* __restrict__ out) {
    extern __shared__ float dynsh[];
    float* ksh  = dynsh;              // [2][4096]
    float* vsh  = dynsh + 8192;       // [2][4096]
    float* wshp = dynsh + 16384;      // [2][64]
    float* ushp = dynsh + 16512;      // [2][64]
    __shared__ float csh[NCHUNK];     // cached g_cmax for this bh
    __shared__ int s_cstart;

    const int bh  = blockIdx.y;
    const int b   = bh >> 3;
    const int n   = bh & 7;
    const int ti  = (int)gridDim.x - 1 - (int)blockIdx.x;  // big tiles first
    const int tid = threadIdx.x;
    const int i   = ti * 128 + tid;

    const uint32_t kb = s2u(ksh);
    const uint32_t vb = kb + 32768u;
    const uint32_t wb = kb + 65536u;
    const uint32_t ub = kb + 66048u;

    // q row in packed registers (32 x f32x2)
    ull qv2[32];
    {
        const float4* qp = (const float4*)q + (b * SS + i) * 128 + n * 16;
        #pragma unroll
        for (int t = 0; t < 16; t++) {
            F4U2 u_; u_.f4 = qp[t];
            qv2[2*t]   = u_.u2[0];
            qv2[2*t+1] = u_.u2[1];
        }
    }

    const float Mi  = g_M[bh * SS + i];
    const int cdiag = i >> 6;
    const int c_end = 2 * ti + 2;

    // preload cmax to smem + ballot-based truncation start (warp 0)
    const float thr = g_M[bh * SS + ti * 128] - 88.0f;
    if (tid < 32) {
        float cmv = g_cmax[bh * NCHUNK + tid];
        csh[tid] = cmv;
        bool liveb = (cmv > thr) && (tid < c_end);
        unsigned msk = __ballot_sync(0xffffffffu, liveb);
        if (tid == 0) {
            int first = msk ? (__ffs(msk) - 1) : (2 * ti);
            s_cstart = (first < 2 * ti) ? first : (2 * ti);
        }
    }
    __syncthreads();
    const int c_start = s_cstart;

#define STAGE(cc, bufidx) do {                                               \
    int j0_ = (cc) * 64;                                                     \
    const float* kp_ = k + (size_t)(b * SS + j0_) * EE + n * 64;             \
    const float* vp_ = v + (size_t)(b * SS + j0_) * EE + n * 64;             \
    _Pragma("unroll")                                                        \
    for (int r_ = 0; r_ < 8; r_++) {                                         \
        int l_ = tid + 128 * r_; int row_ = l_ >> 4, c4_ = l_ & 15;          \
        cp16(kb + (bufidx) * 16384u + (uint32_t)l_ * 16u, kp_ + row_ * EE + c4_ * 4); \
        cp16(vb + (bufidx) * 16384u + (uint32_t)l_ * 16u, vp_ + row_ * EE + c4_ * 4); \
    }                                                                        \
    if (tid < 16)                                                            \
        cp16(wb + (bufidx) * 256u + (uint32_t)tid * 16u, g_w + bh * SS + j0_ + tid * 4); \
    else if (tid < 32)                                                       \
        cp16(ub + (bufidx) * 256u + (uint32_t)(tid - 16) * 16u, g_u + bh * SS + j0_ + (tid - 16) * 4); \
} while (0)

    ull acc2[32];
    #pragma unroll
    for (int t = 0; t < 32; t++) acc2[t] = 0ull;
    float ssum = 0.f;

    STAGE(c_start, 0);
    CP_COMMIT();

    for (int c = c_start; c < c_end; c++) {
        const int cur = (c - c_start) & 1;
        __syncthreads();                       // prior buf consumers done
        if (c + 1 < c_end) STAGE(c + 1, cur ^ 1);
        CP_COMMIT();
        cp_wait<1>();                          // chunk c landed
        __syncthreads();

        const float4* k4s = (const float4*)(ksh + cur * 4096);
        const float4* v4s = (const float4*)(vsh + cur * 4096);

        if (c < cdiag) {
            const float es = __expf(csh[c] - Mi);   // <= 1, from smem
            if (es > 0.f) {
                const float qs = 0.125f * es;
                #pragma unroll 2
                for (int jj = 0; jj < 64; jj++) {
                    const float4* kr = k4s + jj * 16;
                    ull d0 = 0ull, d1 = 0ull, d2 = 0ull, d3 = 0ull;
                    #pragma unroll
                    for (int t = 0; t < 8; t++) {
                        F4U2 ka; ka.f4 = kr[2*t];
                        F4U2 kc; kc.f4 = kr[2*t+1];
                        d0 = fma2(qv2[4*t],   ka.u2[0], d0);
                        d1 = fma2(qv2[4*t+1], ka.u2[1], d1);
                        d2 = fma2(qv2[4*t+2], kc.u2[0], d2);
                        d3 = fma2(qv2[4*t+3], kc.u2[1], d3);
                    }
                    float2 s = unpack2(add2(add2(d0, d1), add2(d2, d3)));
                    float Cv = ((s.x + s.y) * qs) * wshp[cur * 64 + jj];
                    ssum += Cv;
                    ull cv2 = pack2(Cv, Cv);
                    const float4* vr = v4s + jj * 16;
                    #pragma unroll
                    for (int t = 0; t < 16; t++) {
                        F4U2 va; va.f4 = vr[t];
                        acc2[2*t]   = fma2(cv2, va.u2[0], acc2[2*t]);
                        acc2[2*t+1] = fma2(cv2, va.u2[1], acc2[2*t+1]);
                    }
                }
            }
        } else if (c == cdiag) {
            const int j0 = c * 64;
            #pragma unroll 2
            for (int jj = 0; jj < 64; jj++) {
                const float4* kr = k4s + jj * 16;
                ull d0 = 0ull, d1 = 0ull, d2 = 0ull, d3 = 0ull;
                #pragma unroll
                for (int t = 0; t < 8; t++) {
                    F4U2 ka; ka.f4 = kr[2*t];
                    F4U2 kc; kc.f4 = kr[2*t+1];
                    d0 = fma2(qv2[4*t],   ka.u2[0], d0);
                    d1 = fma2(qv2[4*t+1], ka.u2[1], d1);
                    d2 = fma2(qv2[4*t+2], kc.u2[0], d2);
                    d3 = fma2(qv2[4*t+3], kc.u2[1], d3);
                }
                float2 s = unpack2(add2(add2(d0, d1), add2(d2, d3)));
                float qk = (s.x + s.y) * 0.125f;
                float wq = __expf(ushp[cur * 64 + jj] - Mi);
                float Cv = (j0 + jj <= i) ? qk * wq : 0.f;
                ssum += Cv;
                ull cv2 = pack2(Cv, Cv);
                const float4* vr = v4s + jj * 16;
                #pragma unroll
                for (int t = 0; t < 16; t++) {
                    F4U2 va; va.f4 = vr[t];
                    acc2[2*t]   = fma2(cv2, va.u2[0], acc2[2*t]);
                    acc2[2*t+1] = fma2(cv2, va.u2[1], acc2[2*t+1]);
                }
            }
        }
    }
#undef STAGE

    // unpack accumulators
    float accf[64];
    #pragma unroll
    for (int t = 0; t < 32; t++) {
        float2 p = unpack2(acc2[t]);
        accf[2*t]   = p.x;
        accf[2*t+1] = p.y;
    }

    // normalizer: max(|sum C|, exp(-max_log_D)) + eps
    const float mi   = g_m[bh * SS + i];
    const float norm = fmaxf(fabsf(ssum), __expf(-mi)) + 1e-6f;
    const float inv  = 1.0f / norm;

    // LayerNorm over DH (eps = 1e-5, no affine)
    float sum = 0.f;
    #pragma unroll
    for (int t = 0; t < 64; t++) sum += accf[t];
    const float mu = sum * inv * (1.0f / 64.0f);

    float var = 0.f;
    #pragma unroll
    for (int t = 0; t < 64; t++) {
        float dx = accf[t] * inv - mu;
        var += dx * dx;
    }
    var *= (1.0f / 64.0f);
    const float sc = rsqrtf(var + 1e-5f);

    float4* o4 = (float4*)out + (bh * SS + i) * 16;
    #pragma unroll
    for (int t = 0; t < 16; t++) {
        o4[t] = make_float4((accf[4*t]   * inv - mu) * sc,
                            (accf[4*t+1] * inv - mu) * sc,
                            (accf[4*t+2] * inv - mu) * sc,
                            (accf[4*t+3] * inv - mu) * sc);
    }
}

// ---------------------------------------------------------------------------
extern "C" void kernel_launch(void* const* d_in, const int* in_sizes, int n_in,
                              void* d_out, int out_size) {
    const float* q  = (const float*)d_in[0];
    const float* k  = (const float*)d_in[1];
    const float* v  = (const float*)d_in[2];
    const float* Wi = (const float*)d_in[3];
    const float* bi = (const float*)d_in[4];
    const float* Wf = (const float*)d_in[5];
    const float* bf = (const float*)d_in[6];
    float* out = (float*)d_out;

    cudaFuncSetAttribute(attn_kernel,
                         cudaFuncAttributeMaxDynamicSharedMemorySize,
                         ATTN_SMEM_BYTES);

    gates_kernel<<<(BB * SS) / 8, 512>>>(q, k, v, Wi, bi, Wf, bf);
    scan_kernel<<<BH, 256>>>();
    attn_kernel<<<dim3(SS / 128, BH), 128, ATTN_SMEM_BYTES>>>(q, k, v, out);
}

// round 9
// speedup vs baseline: 1.3193x; 1.0563x over previous
#include <cuda_runtime.h>
#include <math.h>
#include <stdint.h>

#define BB 2
#define SS 2048
#define EE 512
#define NHH 8
#define DHH 64
#define BH (BB*NHH)
#define NCHUNK (SS/64)    // 32 chunks of 64

typedef unsigned long long ull;

// Scratch (device globals: allocation-free)
__device__ float g_ig[BH*SS];
__device__ float g_fg[BH*SS];
__device__ float g_u [BH*SS];      // ig_j - cs_j
__device__ float g_M [BH*SS];      // prefix max of u
__device__ float g_m [BH*SS];      // cs_i + M_i (= max_log_D row max)
__device__ float g_w [BH*SS];      // exp(u_j - cmax_of_chunk)
__device__ float g_cmax[BH*NCHUNK];

// ---- packed f32x2 helpers (Blackwell) ----
__device__ __forceinline__ ull fma2(ull a, ull b, ull c) {
    ull d;
    asm("fma.rn.f32x2 %0, %1, %2, %3;" : "=l"(d) : "l"(a), "l"(b), "l"(c));
    return d;
}
__device__ __forceinline__ ull add2(ull a, ull b) {
    ull d;
    asm("add.rn.f32x2 %0, %1, %2;" : "=l"(d) : "l"(a), "l"(b));
    return d;
}
__device__ __forceinline__ ull pack2(float a, float b) {
    ull r;
    asm("mov.b64 %0, {%1, %2};" : "=l"(r) : "f"(a), "f"(b));
    return r;
}
__device__ __forceinline__ float2 unpack2(ull v) {
    float2 r;
    asm("mov.b64 {%0, %1}, %2;" : "=f"(r.x), "=f"(r.y) : "l"(v));
    return r;
}
__device__ __forceinline__ uint32_t s2u(const void* p) {
    uint32_t a;
    asm("{ .reg .u64 t; cvta.to.shared.u64 t, %1; cvt.u32.u64 %0, t; }"
        : "=r"(a) : "l"(p));
    return a;
}
__device__ __forceinline__ void cp16(uint32_t d, const void* s) {
    asm volatile("cp.async.cg.shared.global [%0], [%1], 16;" :: "r"(d), "l"(s));
}
#define CP_COMMIT() asm volatile("cp.async.commit_group;")
template<int N> __device__ __forceinline__ void cp_wait() {
    asm volatile("cp.async.wait_group %0;" :: "n"(N));
}

// ---------------------------------------------------------------------------
// Kernel 1: gate projections (proven 27us version).
// ---------------------------------------------------------------------------
__global__ void __launch_bounds__(512)
gates_kernel(const float* __restrict__ q,
             const float* __restrict__ k,
             const float* __restrict__ v,
             const float* __restrict__ Wi,
             const float* __restrict__ bi,
             const float* __restrict__ Wf,
             const float* __restrict__ bf) {
    __shared__ float gin[8 * 1536];   // 48 KB
    const int tid = threadIdx.x;
    const int r0  = blockIdx.x * 8;

    const float4* q4 = (const float4*)q;
    const float4* k4 = (const float4*)k;
    const float4* v4 = (const float4*)v;
    float4* gin4 = (float4*)gin;
    for (int idx = tid; idx < 8 * 384; idx += 512) {
        int row = idx / 384;
        int c4  = idx - row * 384;
        int r   = r0 + row;
        float4 val;
        if (c4 < 128)       val = q4[r * 128 + c4];
        else if (c4 < 256)  val = k4[r * 128 + (c4 - 128)];
        else                val = v4[r * 128 + (c4 - 256)];
        gin4[row * 384 + c4] = val;
    }
    __syncthreads();

    const int wid  = tid >> 5;
    const int lane = tid & 31;
    const int n    = wid & 7;
    const int isF  = wid >> 3;
    const float* W  = (isF ? Wf : Wi) + n * 1536 + lane;
    const float* g0 = gin + lane;
    const float bias = isF ? bf[n] : bi[n];

    float acc[8] = {0.f, 0.f, 0.f, 0.f, 0.f, 0.f, 0.f, 0.f};
    for (int t = 0; t < 48; t++) {
        float wv = W[t * 32];
        const float* gp = g0 + t * 32;
        #pragma unroll
        for (int r = 0; r < 8; r++) acc[r] += gp[r * 1536] * wv;
    }

    float* dst = isF ? g_fg : g_ig;
    #pragma unroll
    for (int r = 0; r < 8; r++) {
        float a = acc[r];
        #pragma unroll
        for (int o = 16; o > 0; o >>= 1) a += __shfl_xor_sync(0xffffffffu, a, o);
        if (lane == 0) {
            int rr = r0 + r;
            int b = rr / SS, sIdx = rr - b * SS;
            dst[(b * NHH + n) * SS + sIdx] = a + bias;
        }
    }
}

// ---------------------------------------------------------------------------
// Kernel 2: per-(b,n) scan (unchanged).
// ---------------------------------------------------------------------------
__global__ void scan_kernel() {
    __shared__ float sh[256];
    const int bh   = blockIdx.x;
    const int tid  = threadIdx.x;
    const int base = bh * SS + tid * 8;

    float csl[8];
    float run = 0.f;
    #pragma unroll
    for (int t = 0; t < 8; t++) {
        float x  = g_fg[base + t];
        float ls = fminf(x, 0.f) - log1pf(expf(-fabsf(x)));  // log_sigmoid
        run += ls;
        csl[t] = run;
    }
    sh[tid] = run;
    __syncthreads();
    #pragma unroll
    for (int off = 1; off < 256; off <<= 1) {
        float vv = (tid >= off) ? sh[tid - off] : 0.f;
        __syncthreads();
        sh[tid] += vv;
        __syncthreads();
    }
    float offs = (tid > 0) ? sh[tid - 1] : 0.f;

    float u[8], pm[8];
    float runm = -INFINITY;
    #pragma unroll
    for (int t = 0; t < 8; t++) {
        float cs = offs + csl[t];
        csl[t] = cs;
        float ut = g_ig[base + t] - cs;
        u[t] = ut;
        runm = fmaxf(runm, ut);
        pm[t] = runm;
    }
    float cm = runm;
    cm = fmaxf(cm, __shfl_xor_sync(0xffffffffu, cm, 1));
    cm = fmaxf(cm, __shfl_xor_sync(0xffffffffu, cm, 2));
    cm = fmaxf(cm, __shfl_xor_sync(0xffffffffu, cm, 4));
    if ((tid & 7) == 0) g_cmax[bh * NCHUNK + (tid >> 3)] = cm;

    __syncthreads();
    sh[tid] = runm;
    __syncthreads();
    #pragma unroll
    for (int off = 1; off < 256; off <<= 1) {
        float vv = (tid >= off) ? sh[tid - off] : -INFINITY;
        __syncthreads();
        sh[tid] = fmaxf(sh[tid], vv);
        __syncthreads();
    }
    float moffs = (tid > 0) ? sh[tid - 1] : -INFINITY;
    #pragma unroll
    for (int t = 0; t < 8; t++) {
        float Mi = fmaxf(moffs, pm[t]);
        g_u[base + t] = u[t];
        g_M[base + t] = Mi;
        g_m[base + t] = csl[t] + Mi;
        g_w[base + t] = __expf(u[t] - cm);
    }
}

// ---------------------------------------------------------------------------
// Kernel 3: causal decayed attention. R6 skeleton (1 thread/row, 128/block),
// LDS.128 via native ulonglong2 (NOT unions), smem-cached cmax, ballot
// c_start, cp.async double-buffer. grid = (S/128, BH).
// ---------------------------------------------------------------------------
#define ATTN_SMEM_BYTES (16640 * 4)

__global__ void __launch_bounds__(128)
attn_kernel(const float* __restrict__ q,
            const float* __restrict__ k,
            const float* __restrict__ v,
            float* __restrict__ out) {
    extern __shared__ float dynsh[];
    float* ksh  = dynsh;              // [2][4096]
    float* vsh  = dynsh + 8192;       // [2][4096]
    float* wshp = dynsh + 16384;      // [2][64]
    float* ushp = dynsh + 16512;      // [2][64]
    __shared__ float csh[NCHUNK];     // cached g_cmax for this bh
    __shared__ int s_cstart;

    const int bh  = blockIdx.y;
    const int b   = bh >> 3;
    const int n   = bh & 7;
    const int ti  = (int)gridDim.x - 1 - (int)blockIdx.x;  // big tiles first
    const int tid = threadIdx.x;
    const int i   = ti * 128 + tid;

    const uint32_t kb = s2u(ksh);
    const uint32_t vb = kb + 32768u;
    const uint32_t wb = kb + 65536u;
    const uint32_t ub = kb + 66048u;

    // q row in packed registers (32 x f32x2) via native 128-bit loads
    ull qv2[32];
    {
        const ulonglong2* qp =
            (const ulonglong2*)(q + (size_t)(b * SS + i) * EE + n * 64);
        #pragma unroll
        for (int t = 0; t < 16; t++) {
            ulonglong2 val = qp[t];
            qv2[2*t]   = val.x;
            qv2[2*t+1] = val.y;
        }
    }

    const float Mi  = g_M[bh * SS + i];
    const int cdiag = i >> 6;
    const int c_end = 2 * ti + 2;

    // preload cmax to smem + ballot-based truncation start (warp 0)
    const float thr = g_M[bh * SS + ti * 128] - 88.0f;
    if (tid < 32) {
        float cmv = g_cmax[bh * NCHUNK + tid];
        csh[tid] = cmv;
        bool liveb = (cmv > thr) && (tid < c_end);
        unsigned msk = __ballot_sync(0xffffffffu, liveb);
        if (tid == 0) {
            int first = msk ? (__ffs(msk) - 1) : (2 * ti);
            s_cstart = (first < 2 * ti) ? first : (2 * ti);
        }
    }
    __syncthreads();
    const int c_start = s_cstart;

#define STAGE(cc, bufidx) do {                                               \
    int j0_ = (cc) * 64;                                                     \
    const float* kp_ = k + (size_t)(b * SS + j0_) * EE + n * 64;             \
    const float* vp_ = v + (size_t)(b * SS + j0_) * EE + n * 64;             \
    _Pragma("unroll")                                                        \
    for (int r_ = 0; r_ < 8; r_++) {                                         \
        int l_ = tid + 128 * r_; int row_ = l_ >> 4, c4_ = l_ & 15;          \
        cp16(kb + (bufidx) * 16384u + (uint32_t)l_ * 16u, kp_ + row_ * EE + c4_ * 4); \
        cp16(vb + (bufidx) * 16384u + (uint32_t)l_ * 16u, vp_ + row_ * EE + c4_ * 4); \
    }                                                                        \
    if (tid < 16)                                                            \
        cp16(wb + (bufidx) * 256u + (uint32_t)tid * 16u, g_w + bh * SS + j0_ + tid * 4); \
    else if (tid < 32)                                                       \
        cp16(ub + (bufidx) * 256u + (uint32_t)(tid - 16) * 16u, g_u + bh * SS + j0_ + (tid - 16) * 4); \
} while (0)

    ull acc2[32];
    #pragma unroll
    for (int t = 0; t < 32; t++) acc2[t] = 0ull;
    float ssum = 0.f;

    STAGE(c_start, 0);
    CP_COMMIT();

    for (int c = c_start; c < c_end; c++) {
        const int cur = (c - c_start) & 1;
        __syncthreads();                       // prior buf consumers done
        if (c + 1 < c_end) STAGE(c + 1, cur ^ 1);
        CP_COMMIT();
        cp_wait<1>();                          // chunk c landed
        __syncthreads();

        const ulonglong2* k2s = (const ulonglong2*)(ksh + cur * 4096);
        const ulonglong2* v2s = (const ulonglong2*)(vsh + cur * 4096);

        if (c < cdiag) {
            const float es = __expf(csh[c] - Mi);   // <= 1, from smem
            if (es > 0.f) {
                const float qs = 0.125f * es;
                #pragma unroll 2
                for (int jj = 0; jj < 64; jj++) {
                    const ulonglong2* kr = k2s + jj * 16;
                    ull d0 = 0ull, d1 = 0ull, d2 = 0ull, d3 = 0ull;
                    #pragma unroll
                    for (int t = 0; t < 8; t++) {
                        ulonglong2 ka = kr[2*t];
                        ulonglong2 kc = kr[2*t+1];
                        d0 = fma2(qv2[4*t],   ka.x, d0);
                        d1 = fma2(qv2[4*t+1], ka.y, d1);
                        d2 = fma2(qv2[4*t+2], kc.x, d2);
                        d3 = fma2(qv2[4*t+3], kc.y, d3);
                    }
                    float2 s = unpack2(add2(add2(d0, d1), add2(d2, d3)));
                    float Cv = ((s.x + s.y) * qs) * wshp[cur * 64 + jj];
                    ssum += Cv;
                    ull cv2 = pack2(Cv, Cv);
                    const ulonglong2* vr = v2s + jj * 16;
                    #pragma unroll
                    for (int t = 0; t < 16; t++) {
                        ulonglong2 va = vr[t];
                        acc2[2*t]   = fma2(cv2, va.x, acc2[2*t]);
                        acc2[2*t+1] = fma2(cv2, va.y, acc2[2*t+1]);
                    }
                }
            }
        } else if (c == cdiag) {
            const int j0 = c * 64;
            #pragma unroll 2
            for (int jj = 0; jj < 64; jj++) {
                const ulonglong2* kr = k2s + jj * 16;
                ull d0 = 0ull, d1 = 0ull, d2 = 0ull, d3 = 0ull;
                #pragma unroll
                for (int t = 0; t < 8; t++) {
                    ulonglong2 ka = kr[2*t];
                    ulonglong2 kc = kr[2*t+1];
                    d0 = fma2(qv2[4*t],   ka.x, d0);
                    d1 = fma2(qv2[4*t+1], ka.y, d1);
                    d2 = fma2(qv2[4*t+2], kc.x, d2);
                    d3 = fma2(qv2[4*t+3], kc.y, d3);
                }
                float2 s = unpack2(add2(add2(d0, d1), add2(d2, d3)));
                float qk = (s.x + s.y) * 0.125f;
                float wq = __expf(ushp[cur * 64 + jj] - Mi);
                float Cv = (j0 + jj <= i) ? qk * wq : 0.f;
                ssum += Cv;
                ull cv2 = pack2(Cv, Cv);
                const ulonglong2* vr = v2s + jj * 16;
                #pragma unroll
                for (int t = 0; t < 16; t++) {
                    ulonglong2 va = vr[t];
                    acc2[2*t]   = fma2(cv2, va.x, acc2[2*t]);
                    acc2[2*t+1] = fma2(cv2, va.y, acc2[2*t+1]);
                }
            }
        }
    }
#undef STAGE

    // unpack accumulators
    float accf[64];
    #pragma unroll
    for (int t = 0; t < 32; t++) {
        float2 p = unpack2(acc2[t]);
        accf[2*t]   = p.x;
        accf[2*t+1] = p.y;
    }

    // normalizer: max(|sum C|, exp(-max_log_D)) + eps
    const float mi   = g_m[bh * SS + i];
    const float norm = fmaxf(fabsf(ssum), __expf(-mi)) + 1e-6f;
    const float inv  = 1.0f / norm;

    // LayerNorm over DH (eps = 1e-5, no affine)
    float sum = 0.f;
    #pragma unroll
    for (int t = 0; t < 64; t++) sum += accf[t];
    const float mu = sum * inv * (1.0f / 64.0f);

    float var = 0.f;
    #pragma unroll
    for (int t = 0; t < 64; t++) {
        float dx = accf[t] * inv - mu;
        var += dx * dx;
    }
    var *= (1.0f / 64.0f);
    const float sc = rsqrtf(var + 1e-5f);

    float4* o4 = (float4*)out + (bh * SS + i) * 16;
    #pragma unroll
    for (int t = 0; t < 16; t++) {
        o4[t] = make_float4((accf[4*t]   * inv - mu) * sc,
                            (accf[4*t+1] * inv - mu) * sc,
                            (accf[4*t+2] * inv - mu) * sc,
                            (accf[4*t+3] * inv - mu) * sc);
    }
}

// ---------------------------------------------------------------------------
extern "C" void kernel_launch(void* const* d_in, const int* in_sizes, int n_in,
                              void* d_out, int out_size) {
    const float* q  = (const float*)d_in[0];
    const float* k  = (const float*)d_in[1];
    const float* v  = (const float*)d_in[2];
    const float* Wi = (const float*)d_in[3];
    const float* bi = (const float*)d_in[4];
    const float* Wf = (const float*)d_in[5];
    const float* bf = (const float*)d_in[6];
    float* out = (float*)d_out;

    cudaFuncSetAttribute(attn_kernel,
                         cudaFuncAttributeMaxDynamicSharedMemorySize,
                         ATTN_SMEM_BYTES);

    gates_kernel<<<(BB * SS) / 8, 512>>>(q, k, v, Wi, bi, Wf, bf);
    scan_kernel<<<BH, 256>>>();
    attn_kernel<<<dim3(SS / 128, BH), 128, ATTN_SMEM_BYTES>>>(q, k, v, out);
}

// round 10
// speedup vs baseline: 2.7616x; 2.0932x over previous
#include <cuda_runtime.h>
#include <math.h>
#include <stdint.h>

#define BB 2
#define SS 2048
#define EE 512
#define NHH 8
#define BH (BB*NHH)
#define NCHUNK (SS/64)    // 32 chunks of 64

typedef unsigned long long ull;

// Scratch (device globals: allocation-free)
__device__ float g_ig[BH*SS];
__device__ float g_fg[BH*SS];
__device__ float g_u [BH*SS];      // ig_j - cs_j
__device__ float g_M [BH*SS];      // prefix max of u
__device__ float g_m [BH*SS];      // cs_i + M_i (= max_log_D row max)
__device__ float g_w [BH*SS];      // exp(u_j - cmax_of_chunk)
__device__ float g_cmax[BH*NCHUNK];

// ---- packed f32x2 helpers (Blackwell) ----
__device__ __forceinline__ ull fma2(ull a, ull b, ull c) {
    ull d;
    asm("fma.rn.f32x2 %0, %1, %2, %3;" : "=l"(d) : "l"(a), "l"(b), "l"(c));
    return d;
}
__device__ __forceinline__ ull pack2(float a, float b) {
    ull r;
    asm("mov.b64 %0, {%1, %2};" : "=l"(r) : "f"(a), "f"(b));
    return r;
}
__device__ __forceinline__ float2 unpack2(ull v) {
    float2 r;
    asm("mov.b64 {%0, %1}, %2;" : "=f"(r.x), "=f"(r.y) : "l"(v));
    return r;
}
__device__ __forceinline__ uint32_t s2u(const void* p) {
    uint32_t a;
    asm("{ .reg .u64 t; cvta.to.shared.u64 t, %1; cvt.u32.u64 %0, t; }"
        : "=r"(a) : "l"(p));
    return a;
}
__device__ __forceinline__ void cp16(uint32_t d, const void* s) {
    asm volatile("cp.async.cg.shared.global [%0], [%1], 16;" :: "r"(d), "l"(s));
}
#define CP_COMMIT() asm volatile("cp.async.commit_group;")
template<int N> __device__ __forceinline__ void cp_wait() {
    asm volatile("cp.async.wait_group %0;" :: "n"(N));
}

// ---------------------------------------------------------------------------
// Kernel 1: gate projections (proven 27us version, unchanged).
// ---------------------------------------------------------------------------
__global__ void __launch_bounds__(512)
gates_kernel(const float* __restrict__ q,
             const float* __restrict__ k,
             const float* __restrict__ v,
             const float* __restrict__ Wi,
             const float* __restrict__ bi,
             const float* __restrict__ Wf,
             const float* __restrict__ bf) {
    __shared__ float gin[8 * 1536];   // 48 KB
    const int tid = threadIdx.x;
    const int r0  = blockIdx.x * 8;

    const float4* q4 = (const float4*)q;
    const float4* k4 = (const float4*)k;
    const float4* v4 = (const float4*)v;
    float4* gin4 = (float4*)gin;
    for (int idx = tid; idx < 8 * 384; idx += 512) {
        int row = idx / 384;
        int c4  = idx - row * 384;
        int r   = r0 + row;
        float4 val;
        if (c4 < 128)       val = q4[r * 128 + c4];
        else if (c4 < 256)  val = k4[r * 128 + (c4 - 128)];
        else                val = v4[r * 128 + (c4 - 256)];
        gin4[row * 384 + c4] = val;
    }
    __syncthreads();

    const int wid  = tid >> 5;
    const int lane = tid & 31;
    const int n    = wid & 7;
    const int isF  = wid >> 3;
    const float* W  = (isF ? Wf : Wi) + n * 1536 + lane;
    const float* g0 = gin + lane;
    const float bias = isF ? bf[n] : bi[n];

    float acc[8] = {0.f, 0.f, 0.f, 0.f, 0.f, 0.f, 0.f, 0.f};
    for (int t = 0; t < 48; t++) {
        float wv = W[t * 32];
        const float* gp = g0 + t * 32;
        #pragma unroll
        for (int r = 0; r < 8; r++) acc[r] += gp[r * 1536] * wv;
    }

    float* dst = isF ? g_fg : g_ig;
    #pragma unroll
    for (int r = 0; r < 8; r++) {
        float a = acc[r];
        #pragma unroll
        for (int o = 16; o > 0; o >>= 1) a += __shfl_xor_sync(0xffffffffu, a, o);
        if (lane == 0) {
            int rr = r0 + r;
            int b = rr / SS, sIdx = rr - b * SS;
            dst[(b * NHH + n) * SS + sIdx] = a + bias;
        }
    }
}

// ---------------------------------------------------------------------------
// Kernel 2: per-(b,n) scan (unchanged).
// ---------------------------------------------------------------------------
__global__ void scan_kernel() {
    __shared__ float sh[256];
    const int bh   = blockIdx.x;
    const int tid  = threadIdx.x;
    const int base = bh * SS + tid * 8;

    float csl[8];
    float run = 0.f;
    #pragma unroll
    for (int t = 0; t < 8; t++) {
        float x  = g_fg[base + t];
        float ls = fminf(x, 0.f) - log1pf(expf(-fabsf(x)));  // log_sigmoid
        run += ls;
        csl[t] = run;
    }
    sh[tid] = run;
    __syncthreads();
    #pragma unroll
    for (int off = 1; off < 256; off <<= 1) {
        float vv = (tid >= off) ? sh[tid - off] : 0.f;
        __syncthreads();
        sh[tid] += vv;
        __syncthreads();
    }
    float offs = (tid > 0) ? sh[tid - 1] : 0.f;

    float u[8], pm[8];
    float runm = -INFINITY;
    #pragma unroll
    for (int t = 0; t < 8; t++) {
        float cs = offs + csl[t];
        csl[t] = cs;
        float ut = g_ig[base + t] - cs;
        u[t] = ut;
        runm = fmaxf(runm, ut);
        pm[t] = runm;
    }
    float cm = runm;
    cm = fmaxf(cm, __shfl_xor_sync(0xffffffffu, cm, 1));
    cm = fmaxf(cm, __shfl_xor_sync(0xffffffffu, cm, 2));
    cm = fmaxf(cm, __shfl_xor_sync(0xffffffffu, cm, 4));
    if ((tid & 7) == 0) g_cmax[bh * NCHUNK + (tid >> 3)] = cm;

    __syncthreads();
    sh[tid] = runm;
    __syncthreads();
    #pragma unroll
    for (int off = 1; off < 256; off <<= 1) {
        float vv = (tid >= off) ? sh[tid - off] : -INFINITY;
        __syncthreads();
        sh[tid] = fmaxf(sh[tid], vv);
        __syncthreads();
    }
    float moffs = (tid > 0) ? sh[tid - 1] : -INFINITY;
    #pragma unroll
    for (int t = 0; t < 8; t++) {
        float Mi = fmaxf(moffs, pm[t]);
        g_u[base + t] = u[t];
        g_M[base + t] = Mi;
        g_m[base + t] = csl[t] + Mi;
        g_w[base + t] = __expf(u[t] - cm);
    }
}

// ---------------------------------------------------------------------------
// Kernel 3: register-tiled two-phase GEMM attention.
// Block = 64 query rows (one bh), 256 threads, thread tile 4i x 4j / 4i x 4d.
// GEMM1: S=Q.K^T from transposed smem (outer products over d).
// scale/mask -> P staged transposed to smem. GEMM2: O += P.V (outer over j).
// cp.async prefetch of next chunk overlapped under compute.
// ---------------------------------------------------------------------------
// smem float offsets (all 16B-aligned)
#define OFF_QT    0          // Qt[64][68]   (d-major, pad 68)
#define OFF_KT    4352       // Kt[64][68]
#define OFF_KTMP  8704       // Ktmp[64][68] (staging, padded rows)
#define OFF_V     13056      // V[2][64][64] (j-major)
#define OFF_PT    21248      // Pt[64][68]   (j-major rows of i)
#define OFF_W     25600      // w[2][64]
#define OFF_U     25728      // u[2][64]
#define OFF_CS    25856      // cmax[32]
#define ATTN_SMEM_FLOATS 25888
#define ATTN_SMEM_BYTES (ATTN_SMEM_FLOATS * 4)

__global__ void __launch_bounds__(256, 2)
attn_kernel(const float* __restrict__ q,
            const float* __restrict__ k,
            const float* __restrict__ v,
            float* __restrict__ out) {
    extern __shared__ float sm[];
    __shared__ int s_cstart;

    float* Qt   = sm + OFF_QT;
    float* Kt   = sm + OFF_KT;
    float* Ktmp = sm + OFF_KTMP;
    float* Vb   = sm + OFF_V;
    float* Pt   = sm + OFF_PT;
    float* Wb   = sm + OFF_W;
    float* Ub   = sm + OFF_U;
    float* Cs   = sm + OFF_CS;

    const int bh  = blockIdx.y;
    const int b   = bh >> 3;
    const int n   = bh & 7;
    const int ti  = (int)gridDim.x - 1 - (int)blockIdx.x;  // 0..31, big first
    const int tid = threadIdx.x;
    const int tx  = tid & 15;        // j/d tile (4 cols)
    const int ty  = tid >> 4;        // i tile (4 rows)

    const uint32_t ktmp_a = s2u(Ktmp);
    const uint32_t v_a    = s2u(Vb);
    const uint32_t w_a    = s2u(Wb);
    const uint32_t u_a    = s2u(Ub);

    const int i0 = ti * 64;
    const float* qg  = q + (size_t)(b * SS + i0) * EE + n * 64;
    const float* kg0 = k + (size_t)(b * SS) * EE + n * 64;
    const float* vg0 = v + (size_t)(b * SS) * EE + n * 64;

    // per-thread row maxima M_i (i = i0 + ty*4 + r)
    float Mr[4];
    #pragma unroll
    for (int r = 0; r < 4; r++) Mr[r] = g_M[bh * SS + i0 + ty * 4 + r];

    // cmax cache + truncation start via ballot (warp 0)
    const float thr = g_M[bh * SS + i0] - 88.0f;
    if (tid < 32) {
        float cmv = g_cmax[bh * NCHUNK + tid];
        Cs[tid] = cmv;
        bool liveb = (cmv > thr) && (tid < ti);
        unsigned msk = __ballot_sync(0xffffffffu, liveb);
        if (tid == 0) s_cstart = msk ? (__ffs(msk) - 1) : ti;
    }

    // --- prologue: stage Q (group A) ---
    #pragma unroll
    for (int t = 0; t < 4; t++) {
        int s = tid + 256 * t, row = s >> 4, c16 = s & 15;
        cp16(ktmp_a + (uint32_t)(row * 272 + c16 * 16), qg + row * EE + c16 * 4);
    }
    CP_COMMIT();
    __syncthreads();                     // s_cstart/Cs visible
    const int c_start = s_cstart;
    const int j00 = c_start * 64;

    // group B: V(c0) -> Vb[0], w/u(c0) -> buf 0
    #pragma unroll
    for (int t = 0; t < 4; t++) {
        int s = tid + 256 * t, row = s >> 4, c16 = s & 15;
        cp16(v_a + (uint32_t)(s * 16), vg0 + (size_t)(j00 + row) * EE + c16 * 4);
    }
    if (tid < 16)      cp16(w_a + tid * 16u, g_w + bh * SS + j00 + tid * 4);
    else if (tid < 32) cp16(u_a + (tid - 16) * 16u, g_u + bh * SS + j00 + (tid - 16) * 4);
    CP_COMMIT();
    cp_wait<1>();                        // group A (Q) landed
    __syncthreads();

    // transpose staged Q -> Qt
    {
        int jr = tid & 63, db = tid >> 6;
        #pragma unroll
        for (int e4 = 0; e4 < 4; e4++) {
            float4 val = *(const float4*)(Ktmp + jr * 68 + db * 16 + e4 * 4);
            int d = db * 16 + e4 * 4;
            Qt[(d + 0) * 68 + jr] = val.x;
            Qt[(d + 1) * 68 + jr] = val.y;
            Qt[(d + 2) * 68 + jr] = val.z;
            Qt[(d + 3) * 68 + jr] = val.w;
        }
    }
    __syncthreads();

    // group C: K(c0) -> Ktmp
    #pragma unroll
    for (int t = 0; t < 4; t++) {
        int s = tid + 256 * t, row = s >> 4, c16 = s & 15;
        cp16(ktmp_a + (uint32_t)(row * 272 + c16 * 16),
             kg0 + (size_t)(j00 + row) * EE + c16 * 4);
    }
    CP_COMMIT();
    cp_wait<0>();
    __syncthreads();
    {   // transpose K -> Kt
        int jr = tid & 63, db = tid >> 6;
        #pragma unroll
        for (int e4 = 0; e4 < 4; e4++) {
            float4 val = *(const float4*)(Ktmp + jr * 68 + db * 16 + e4 * 4);
            int d = db * 16 + e4 * 4;
            Kt[(d + 0) * 68 + jr] = val.x;
            Kt[(d + 1) * 68 + jr] = val.y;
            Kt[(d + 2) * 68 + jr] = val.z;
            Kt[(d + 3) * 68 + jr] = val.w;
        }
    }
    __syncthreads();

    ull o2[4][2];
    #pragma unroll
    for (int r = 0; r < 4; r++) { o2[r][0] = 0ull; o2[r][1] = 0ull; }
    float ssum[4] = {0.f, 0.f, 0.f, 0.f};

    for (int c = c_start; c <= ti; c++) {
        const int p = (c - c_start) & 1;

        // prefetch chunk c+1 (K -> Ktmp, V/w/u -> alt buffers)
        if (c < ti) {
            const int j1 = (c + 1) * 64;
            const uint32_t vdst = v_a + (uint32_t)((p ^ 1) * 16384);
            #pragma unroll
            for (int t = 0; t < 4; t++) {
                int s = tid + 256 * t, row = s >> 4, c16 = s & 15;
                cp16(ktmp_a + (uint32_t)(row * 272 + c16 * 16),
                     kg0 + (size_t)(j1 + row) * EE + c16 * 4);
                cp16(vdst + (uint32_t)(s * 16),
                     vg0 + (size_t)(j1 + row) * EE + c16 * 4);
            }
            if (tid < 16)
                cp16(w_a + (p ^ 1) * 256u + tid * 16u, g_w + bh * SS + j1 + tid * 4);
            else if (tid < 32)
                cp16(u_a + (p ^ 1) * 256u + (tid - 16) * 16u,
                     g_u + bh * SS + j1 + (tid - 16) * 4);
            CP_COMMIT();
        }

        // ---- GEMM1: S[4i][4j] over d (outer products) ----
        ull s2[4][2];
        #pragma unroll
        for (int r = 0; r < 4; r++) { s2[r][0] = 0ull; s2[r][1] = 0ull; }
        {
            const float* QtB = Qt + ty * 4;
            const float* KtB = Kt + tx * 4;
            #pragma unroll 4
            for (int d = 0; d < 64; d++) {
                float4 q4 = *(const float4*)(QtB + d * 68);
                ulonglong2 k2 = *(const ulonglong2*)(KtB + d * 68);
                ull qb;
                qb = pack2(q4.x, q4.x);
                s2[0][0] = fma2(qb, k2.x, s2[0][0]);
                s2[0][1] = fma2(qb, k2.y, s2[0][1]);
                qb = pack2(q4.y, q4.y);
                s2[1][0] = fma2(qb, k2.x, s2[1][0]);
                s2[1][1] = fma2(qb, k2.y, s2[1][1]);
                qb = pack2(q4.z, q4.z);
                s2[2][0] = fma2(qb, k2.x, s2[2][0]);
                s2[2][1] = fma2(qb, k2.y, s2[2][1]);
                qb = pack2(q4.w, q4.w);
                s2[3][0] = fma2(qb, k2.x, s2[3][0]);
                s2[3][1] = fma2(qb, k2.y, s2[3][1]);
            }
        }

        // ---- scale/mask -> P, write Pt, accumulate ssum ----
        float P[4][4];
        if (c < ti) {
            const float cval = Cs[c];
            float4 wv = *(const float4*)(Wb + p * 64 + tx * 4);
            #pragma unroll
            for (int r = 0; r < 4; r++) {
                float qs = 0.125f * __expf(cval - Mr[r]);   // <= 0.125
                float2 a = unpack2(s2[r][0]);
                float2 bq = unpack2(s2[r][1]);
                P[r][0] = a.x * qs * wv.x;
                P[r][1] = a.y * qs * wv.y;
                P[r][2] = bq.x * qs * wv.z;
                P[r][3] = bq.y * qs * wv.w;
            }
        } else {
            // diagonal chunk: exact per-(i,j) exponent + causal mask
            float4 uv = *(const float4*)(Ub + p * 64 + tx * 4);
            #pragma unroll
            for (int r = 0; r < 4; r++) {
                int iloc = ty * 4 + r;
                float2 a = unpack2(s2[r][0]);
                float2 bq = unpack2(s2[r][1]);
                float p0 = a.x * 0.125f * __expf(uv.x - Mr[r]);
                float p1 = a.y * 0.125f * __expf(uv.y - Mr[r]);
                float p2 = bq.x * 0.125f * __expf(uv.z - Mr[r]);
                float p3 = bq.y * 0.125f * __expf(uv.w - Mr[r]);
                P[r][0] = (tx * 4 + 0 <= iloc) ? p0 : 0.f;
                P[r][1] = (tx * 4 + 1 <= iloc) ? p1 : 0.f;
                P[r][2] = (tx * 4 + 2 <= iloc) ? p2 : 0.f;
                P[r][3] = (tx * 4 + 3 <= iloc) ? p3 : 0.f;
            }
        }
        #pragma unroll
        for (int s_ = 0; s_ < 4; s_++) {
            float4 col = make_float4(P[0][s_], P[1][s_], P[2][s_], P[3][s_]);
            *(float4*)(Pt + (tx * 4 + s_) * 68 + ty * 4) = col;
        }
        #pragma unroll
        for (int r = 0; r < 4; r++) {
            float pr = (P[r][0] + P[r][1]) + (P[r][2] + P[r][3]);
            pr += __shfl_xor_sync(0xffffffffu, pr, 1);
            pr += __shfl_xor_sync(0xffffffffu, pr, 2);
            pr += __shfl_xor_sync(0xffffffffu, pr, 4);
            pr += __shfl_xor_sync(0xffffffffu, pr, 8);
            ssum[r] += pr;
        }
        __syncthreads();                 // Pt complete

        // ---- GEMM2: O[4i][4d] += P.V over j (outer products) ----
        {
            const float* PtB = Pt + ty * 4;
            const float* VbB = Vb + p * 4096 + tx * 4;
            #pragma unroll 4
            for (int j = 0; j < 64; j++) {
                float4 p4 = *(const float4*)(PtB + j * 68);
                ulonglong2 v2r = *(const ulonglong2*)(VbB + j * 64);
                ull pb;
                pb = pack2(p4.x, p4.x);
                o2[0][0] = fma2(pb, v2r.x, o2[0][0]);
                o2[0][1] = fma2(pb, v2r.y, o2[0][1]);
                pb = pack2(p4.y, p4.y);
                o2[1][0] = fma2(pb, v2r.x, o2[1][0]);
                o2[1][1] = fma2(pb, v2r.y, o2[1][1]);
                pb = pack2(p4.z, p4.z);
                o2[2][0] = fma2(pb, v2r.x, o2[2][0]);
                o2[2][1] = fma2(pb, v2r.y, o2[2][1]);
                pb = pack2(p4.w, p4.w);
                o2[3][0] = fma2(pb, v2r.x, o2[3][0]);
                o2[3][1] = fma2(pb, v2r.y, o2[3][1]);
            }
        }

        cp_wait<0>();
        __syncthreads();                 // GEMM1/2 readers done; prefetch landed
        if (c < ti) {                    // transpose next K -> Kt
            int jr = tid & 63, db = tid >> 6;
            #pragma unroll
            for (int e4 = 0; e4 < 4; e4++) {
                float4 val = *(const float4*)(Ktmp + jr * 68 + db * 16 + e4 * 4);
                int d = db * 16 + e4 * 4;
                Kt[(d + 0) * 68 + jr] = val.x;
                Kt[(d + 1) * 68 + jr] = val.y;
                Kt[(d + 2) * 68 + jr] = val.z;
                Kt[(d + 3) * 68 + jr] = val.w;
            }
            __syncthreads();
        }
    }

    // ---- epilogue: normalizer + LayerNorm + store ----
    #pragma unroll
    for (int r = 0; r < 4; r++) {
        const int i = i0 + ty * 4 + r;
        float2 pa = unpack2(o2[r][0]);
        float2 pb = unpack2(o2[r][1]);
        float of0 = pa.x, of1 = pa.y, of2 = pb.x, of3 = pb.y;

        const float mi   = g_m[bh * SS + i];
        const float norm = fmaxf(fabsf(ssum[r]), __expf(-mi)) + 1e-6f;
        const float inv  = 1.0f / norm;

        float hs = (of0 + of1) + (of2 + of3);
        hs += __shfl_xor_sync(0xffffffffu, hs, 1);
        hs += __shfl_xor_sync(0xffffffffu, hs, 2);
        hs += __shfl_xor_sync(0xffffffffu, hs, 4);
        hs += __shfl_xor_sync(0xffffffffu, hs, 8);
        const float mu = hs * inv * (1.0f / 64.0f);

        float d0 = of0 * inv - mu, d1 = of1 * inv - mu;
        float d2 = of2 * inv - mu, d3 = of3 * inv - mu;
        float vr = d0 * d0 + d1 * d1 + d2 * d2 + d3 * d3;
        vr += __shfl_xor_sync(0xffffffffu, vr, 1);
        vr += __shfl_xor_sync(0xffffffffu, vr, 2);
        vr += __shfl_xor_sync(0xffffffffu, vr, 4);
        vr += __shfl_xor_sync(0xffffffffu, vr, 8);
        const float sc = rsqrtf(vr * (1.0f / 64.0f) + 1e-5f);

        *(float4*)(out + (size_t)(bh * SS + i) * 64 + tx * 4) =
            make_float4(d0 * sc, d1 * sc, d2 * sc, d3 * sc);
    }
}

// ---------------------------------------------------------------------------
extern "C" void kernel_launch(void* const* d_in, const int* in_sizes, int n_in,
                              void* d_out, int out_size) {
    const float* q  = (const float*)d_in[0];
    const float* k  = (const float*)d_in[1];
    const float* v  = (const float*)d_in[2];
    const float* Wi = (const float*)d_in[3];
    const float* bi = (const float*)d_in[4];
    const float* Wf = (const float*)d_in[5];
    const float* bf = (const float*)d_in[6];
    float* out = (float*)d_out;

    cudaFuncSetAttribute(attn_kernel,
                         cudaFuncAttributeMaxDynamicSharedMemorySize,
                         ATTN_SMEM_BYTES);

    gates_kernel<<<(BB * SS) / 8, 512>>>(q, k, v, Wi, bi, Wf, bf);
    scan_kernel<<<BH, 256>>>();
    attn_kernel<<<dim3(SS / 64, BH), 256, ATTN_SMEM_BYTES>>>(q, k, v, out);
}

// round 12
// speedup vs baseline: 4.7396x; 1.7163x over previous
#include <cuda_runtime.h>
#include <math.h>
#include <stdint.h>

#define BB 2
#define SS 2048
#define EE 512
#define NHH 8
#define BH (BB*NHH)
#define NCHUNK (SS/64)

typedef unsigned long long ull;

// Scratch (device globals: allocation-free)
__device__ float g_ig[BH*SS];
__device__ float g_fg[BH*SS];
__device__ float g_u [BH*SS];      // ig_j - cs_j
__device__ float g_M [BH*SS];      // prefix max of u
__device__ float g_m [BH*SS];      // cs_i + M_i
__device__ float g_w [BH*SS];      // exp(u_j - cmax_of_chunk)
__device__ float g_cmax[BH*NCHUNK];

__device__ __forceinline__ uint32_t s2u(const void* p) {
    uint32_t a;
    asm("{ .reg .u64 t; cvta.to.shared.u64 t, %1; cvt.u32.u64 %0, t; }"
        : "=r"(a) : "l"(p));
    return a;
}
__device__ __forceinline__ void cp16(uint32_t d, const void* s) {
    asm volatile("cp.async.cg.shared.global [%0], [%1], 16;" :: "r"(d), "l"(s));
}
#define CP_COMMIT() asm volatile("cp.async.commit_group;")
template<int N> __device__ __forceinline__ void cp_wait() {
    asm volatile("cp.async.wait_group %0;" :: "n"(N));
}

// m16n8k8 tf32 mma (row-major A, col-major B), accumulate in place
__device__ __forceinline__ void mma_tf32(float& d0, float& d1, float& d2, float& d3,
                                         uint32_t a0, uint32_t a1, uint32_t a2, uint32_t a3,
                                         uint32_t b0, uint32_t b1) {
    asm volatile(
        "mma.sync.aligned.m16n8k8.row.col.f32.tf32.tf32.f32 "
        "{%0,%1,%2,%3}, {%4,%5,%6,%7}, {%8,%9}, {%0,%1,%2,%3};"
        : "+f"(d0), "+f"(d1), "+f"(d2), "+f"(d3)
        : "r"(a0), "r"(a1), "r"(a2), "r"(a3), "r"(b0), "r"(b1));
}

// ---------------------------------------------------------------------------
// Kernel 1: gate projections (proven 27us version, unchanged).
// ---------------------------------------------------------------------------
__global__ void __launch_bounds__(512)
gates_kernel(const float* __restrict__ q,
             const float* __restrict__ k,
             const float* __restrict__ v,
             const float* __restrict__ Wi,
             const float* __restrict__ bi,
             const float* __restrict__ Wf,
             const float* __restrict__ bf) {
    __shared__ float gin[8 * 1536];   // 48 KB
    const int tid = threadIdx.x;
    const int r0  = blockIdx.x * 8;

    const float4* q4 = (const float4*)q;
    const float4* k4 = (const float4*)k;
    const float4* v4 = (const float4*)v;
    float4* gin4 = (float4*)gin;
    for (int idx = tid; idx < 8 * 384; idx += 512) {
        int row = idx / 384;
        int c4  = idx - row * 384;
        int r   = r0 + row;
        float4 val;
        if (c4 < 128)       val = q4[r * 128 + c4];
        else if (c4 < 256)  val = k4[r * 128 + (c4 - 128)];
        else                val = v4[r * 128 + (c4 - 256)];
        gin4[row * 384 + c4] = val;
    }
    __syncthreads();

    const int wid  = tid >> 5;
    const int lane = tid & 31;
    const int n    = wid & 7;
    const int isF  = wid >> 3;
    const float* W  = (isF ? Wf : Wi) + n * 1536 + lane;
    const float* g0 = gin + lane;
    const float bias = isF ? bf[n] : bi[n];

    float acc[8] = {0.f, 0.f, 0.f, 0.f, 0.f, 0.f, 0.f, 0.f};
    for (int t = 0; t < 48; t++) {
        float wv = W[t * 32];
        const float* gp = g0 + t * 32;
        #pragma unroll
        for (int r = 0; r < 8; r++) acc[r] += gp[r * 1536] * wv;
    }

    float* dst = isF ? g_fg : g_ig;
    #pragma unroll
    for (int r = 0; r < 8; r++) {
        float a = acc[r];
        #pragma unroll
        for (int o = 16; o > 0; o >>= 1) a += __shfl_xor_sync(0xffffffffu, a, o);
        if (lane == 0) {
            int rr = r0 + r;
            int b = rr / SS, sIdx = rr - b * SS;
            dst[(b * NHH + n) * SS + sIdx] = a + bias;
        }
    }
}

// ---------------------------------------------------------------------------
// Kernel 2: per-(b,n) scan (unchanged).
// ---------------------------------------------------------------------------
__global__ void scan_kernel() {
    __shared__ float sh[256];
    const int bh   = blockIdx.x;
    const int tid  = threadIdx.x;
    const int base = bh * SS + tid * 8;

    float csl[8];
    float run = 0.f;
    #pragma unroll
    for (int t = 0; t < 8; t++) {
        float x  = g_fg[base + t];
        float ls = fminf(x, 0.f) - log1pf(expf(-fabsf(x)));
        run += ls;
        csl[t] = run;
    }
    sh[tid] = run;
    __syncthreads();
    #pragma unroll
    for (int off = 1; off < 256; off <<= 1) {
        float vv = (tid >= off) ? sh[tid - off] : 0.f;
        __syncthreads();
        sh[tid] += vv;
        __syncthreads();
    }
    float offs = (tid > 0) ? sh[tid - 1] : 0.f;

    float u[8], pm[8];
    float runm = -INFINITY;
    #pragma unroll
    for (int t = 0; t < 8; t++) {
        float cs = offs + csl[t];
        csl[t] = cs;
        float ut = g_ig[base + t] - cs;
        u[t] = ut;
        runm = fmaxf(runm, ut);
        pm[t] = runm;
    }
    float cm = runm;
    cm = fmaxf(cm, __shfl_xor_sync(0xffffffffu, cm, 1));
    cm = fmaxf(cm, __shfl_xor_sync(0xffffffffu, cm, 2));
    cm = fmaxf(cm, __shfl_xor_sync(0xffffffffu, cm, 4));
    if ((tid & 7) == 0) g_cmax[bh * NCHUNK + (tid >> 3)] = cm;

    __syncthreads();
    sh[tid] = runm;
    __syncthreads();
    #pragma unroll
    for (int off = 1; off < 256; off <<= 1) {
        float vv = (tid >= off) ? sh[tid - off] : -INFINITY;
        __syncthreads();
        sh[tid] = fmaxf(sh[tid], vv);
        __syncthreads();
    }
    float moffs = (tid > 0) ? sh[tid - 1] : -INFINITY;
    #pragma unroll
    for (int t = 0; t < 8; t++) {
        float Mi = fmaxf(moffs, pm[t]);
        g_u[base + t] = u[t];
        g_M[base + t] = Mi;
        g_m[base + t] = csl[t] + Mi;
        g_w[base + t] = __expf(u[t] - cm);
    }
}

// ---------------------------------------------------------------------------
// Kernel 3: tf32 mma.sync attention. Block = 64 query rows, 256 threads
// (8 warps as 4 i-blocks x 2 jd-halves). No smem transposes: fragment
// mappings read row-major tiles conflict-free (Q/K/P pad 68, V pad 72).
// ---------------------------------------------------------------------------
// smem float offsets
#define QS_OFF 0          // Qs[64][68]
#define KS_OFF 4352       // Ks[2][64][68]
#define VS_OFF 13056      // Vs[2][64][72]
#define PS_OFF 22272      // Ps[64][68] (also O staging in epilogue)
#define WB_OFF 26624      // Wb[2][64]
#define UB_OFF 26752      // Ub[2][64]
#define MS_OFF 26880      // Ms[64]
#define CS_OFF 26944      // Cs[32]
#define ATTN_SMEM_FLOATS 26976
#define ATTN_SMEM_BYTES (ATTN_SMEM_FLOATS * 4)

__global__ void __launch_bounds__(256, 2)
attn_kernel(const float* __restrict__ q,
            const float* __restrict__ k,
            const float* __restrict__ v,
            float* __restrict__ out) {
    extern __shared__ float sm[];
    __shared__ int s_cstart;

    const int bh  = blockIdx.y;
    const int b   = bh >> 3;
    const int n   = bh & 7;
    const int ti  = (int)gridDim.x - 1 - (int)blockIdx.x;   // big tiles first
    const int tid = threadIdx.x;
    const int lane = tid & 31;
    const int wi  = (tid >> 5) & 3;      // i-block (16 rows)
    const int wj  = tid >> 7;            // j/d half (32 cols)
    const int g8  = lane >> 2;           // fragment group 0..7
    const int tg  = lane & 3;            // thread-in-group 0..3
    const int i0w = wi * 16;

    const int i0 = ti * 64;
    const float* qg  = q + (size_t)(b * SS + i0) * EE + n * 64;
    const float* kg0 = k + (size_t)(b * SS) * EE + n * 64;
    const float* vg0 = v + (size_t)(b * SS) * EE + n * 64;

    const uint32_t qs_a = s2u(sm + QS_OFF);
    const uint32_t ks_a = s2u(sm + KS_OFF);
    const uint32_t vs_a = s2u(sm + VS_OFF);
    const uint32_t wb_a = s2u(sm + WB_OFF);
    const uint32_t ub_a = s2u(sm + UB_OFF);
    const uint32_t ms_a = s2u(sm + MS_OFF);

    // warp 0: cmax cache + truncation-start ballot
    if (tid < 32) {
        float thr = g_M[bh * SS + i0] - 88.0f;
        float cmv = g_cmax[bh * NCHUNK + tid];
        sm[CS_OFF + tid] = cmv;
        bool live = (cmv > thr) && (tid < ti);
        unsigned msk = __ballot_sync(0xffffffffu, live);
        if (tid == 0) s_cstart = msk ? (__ffs(msk) - 1) : ti;
    }

    // group A: Q + Ms
    #pragma unroll
    for (int t = 0; t < 4; t++) {
        int s = tid + 256 * t, row = s >> 4, c16 = s & 15;
        cp16(qs_a + (uint32_t)(row * 272 + c16 * 16), qg + row * EE + c16 * 4);
    }
    if (tid < 16) cp16(ms_a + tid * 16u, g_M + bh * SS + i0 + tid * 4);
    CP_COMMIT();
    cp_wait<0>();
    __syncthreads();

    const int c_start = s_cstart;
    const float M0 = sm[MS_OFF + i0w + g8];
    const float M1 = sm[MS_OFF + i0w + g8 + 8];

#define STAGE_CH(cc, bufidx) do {                                             \
    int j0_ = (cc) * 64;                                                      \
    _Pragma("unroll")                                                         \
    for (int t_ = 0; t_ < 4; t_++) {                                          \
        int s_ = tid + 256 * t_, row_ = s_ >> 4, c16_ = s_ & 15;              \
        cp16(ks_a + (uint32_t)((bufidx) * 17408 + row_ * 272 + c16_ * 16),    \
             kg0 + (size_t)(j0_ + row_) * EE + c16_ * 4);                     \
        cp16(vs_a + (uint32_t)((bufidx) * 18432 + row_ * 288 + c16_ * 16),    \
             vg0 + (size_t)(j0_ + row_) * EE + c16_ * 4);                     \
    }                                                                         \
    if (tid < 16)                                                             \
        cp16(wb_a + (bufidx) * 256u + tid * 16u, g_w + bh * SS + j0_ + tid * 4); \
    else if (tid < 32)                                                        \
        cp16(ub_a + (bufidx) * 256u + (tid - 16) * 16u,                       \
             g_u + bh * SS + j0_ + (tid - 16) * 4);                           \
} while (0)

    STAGE_CH(c_start, 0);
    CP_COMMIT();

    float o[4][4];
    #pragma unroll
    for (int t = 0; t < 4; t++)
        #pragma unroll
        for (int r = 0; r < 4; r++) o[t][r] = 0.f;
    float ssum_part = 0.f;

    for (int c = c_start; c <= ti; c++) {
        const int p = (c - c_start) & 1;
        __syncthreads();                 // prev-iter reads of Vs[p^1]/Ps done
        if (c < ti) {
            STAGE_CH(c + 1, p ^ 1);
            CP_COMMIT();
            cp_wait<1>();
        } else {
            cp_wait<0>();
        }
        __syncthreads();                 // chunk c visible

        const float* Ksp = sm + KS_OFF + p * 4352;
        const float* Vsp = sm + VS_OFF + p * 4608;

        // ---- GEMM1: S = Q.K^T (tf32 mma) ----
        float s4[4][4];
        #pragma unroll
        for (int t = 0; t < 4; t++)
            #pragma unroll
            for (int r = 0; r < 4; r++) s4[t][r] = 0.f;
        #pragma unroll
        for (int ks = 0; ks < 8; ks++) {
            const int k0 = ks * 8;
            const float* qb = sm + QS_OFF + (i0w + g8) * 68 + k0 + tg;
            uint32_t a0 = __float_as_uint(qb[0]);
            uint32_t a1 = __float_as_uint(qb[8 * 68]);
            uint32_t a2 = __float_as_uint(qb[4]);
            uint32_t a3 = __float_as_uint(qb[8 * 68 + 4]);
            #pragma unroll
            for (int t = 0; t < 4; t++) {
                const int j0 = wj * 32 + t * 8;
                const float* kbp = Ksp + (j0 + g8) * 68 + k0 + tg;
                uint32_t b0 = __float_as_uint(kbp[0]);
                uint32_t b1 = __float_as_uint(kbp[4]);
                mma_tf32(s4[t][0], s4[t][1], s4[t][2], s4[t][3],
                         a0, a1, a2, a3, b0, b1);
            }
        }

        // ---- P = scale(S), store to Ps ----
        if (c < ti) {
            const float csc = sm[CS_OFF + c];
            const float e0 = 0.125f * __expf(csc - M0);
            const float e1 = 0.125f * __expf(csc - M1);
            #pragma unroll
            for (int t = 0; t < 4; t++) {
                const int jc = wj * 32 + t * 8 + tg * 2;
                float2 wv = *(const float2*)(sm + WB_OFF + p * 64 + jc);
                float2 hi = make_float2(s4[t][0] * e0 * wv.x, s4[t][1] * e0 * wv.y);
                float2 lo = make_float2(s4[t][2] * e1 * wv.x, s4[t][3] * e1 * wv.y);
                *(float2*)(sm + PS_OFF + (i0w + g8) * 68 + jc)     = hi;
                *(float2*)(sm + PS_OFF + (i0w + g8 + 8) * 68 + jc) = lo;
            }
        } else {
            const int il0 = i0w + g8, il1 = il0 + 8;
            #pragma unroll
            for (int t = 0; t < 4; t++) {
                const int jc = wj * 32 + t * 8 + tg * 2;
                float2 uv = *(const float2*)(sm + UB_OFF + p * 64 + jc);
                float p0 = (jc     <= il0) ? s4[t][0] * 0.125f * __expf(uv.x - M0) : 0.f;
                float p1 = (jc + 1 <= il0) ? s4[t][1] * 0.125f * __expf(uv.y - M0) : 0.f;
                float p2 = (jc     <= il1) ? s4[t][2] * 0.125f * __expf(uv.x - M1) : 0.f;
                float p3 = (jc + 1 <= il1) ? s4[t][3] * 0.125f * __expf(uv.y - M1) : 0.f;
                *(float2*)(sm + PS_OFF + (i0w + g8) * 68 + jc)     = make_float2(p0, p1);
                *(float2*)(sm + PS_OFF + (i0w + g8 + 8) * 68 + jc) = make_float2(p2, p3);
            }
        }
        __syncthreads();                 // Ps complete

        // ---- ssum partial (row = tid>>2, quarter = tid&3) ----
        {
            const int srow = tid >> 2, sq = tid & 3;
            const float4* pr = (const float4*)(sm + PS_OFF + srow * 68 + sq * 16);
            float4 x0 = pr[0], x1 = pr[1], x2 = pr[2], x3 = pr[3];
            ssum_part += (((x0.x + x0.y) + (x0.z + x0.w))
                        + ((x1.x + x1.y) + (x1.z + x1.w)))
                       + (((x2.x + x2.y) + (x2.z + x2.w))
                        + ((x3.x + x3.y) + (x3.z + x3.w)));
        }

        // ---- GEMM2: O += P.V (tf32 mma) ----
        #pragma unroll
        for (int ks = 0; ks < 8; ks++) {
            const int k0j = ks * 8;
            const float* pb = sm + PS_OFF + (i0w + g8) * 68 + k0j + tg;
            uint32_t a0 = __float_as_uint(pb[0]);
            uint32_t a1 = __float_as_uint(pb[8 * 68]);
            uint32_t a2 = __float_as_uint(pb[4]);
            uint32_t a3 = __float_as_uint(pb[8 * 68 + 4]);
            #pragma unroll
            for (int t = 0; t < 4; t++) {
                const int d0c = wj * 32 + t * 8;
                const float* vbp = Vsp + (k0j + tg) * 72 + d0c + g8;
                uint32_t b0 = __float_as_uint(vbp[0]);
                uint32_t b1 = __float_as_uint(vbp[4 * 72]);
                mma_tf32(o[t][0], o[t][1], o[t][2], o[t][3],
                         a0, a1, a2, a3, b0, b1);
            }
        }
    }
#undef STAGE_CH

    // ---- epilogue ----
    __syncthreads();                     // last GEMM2 reads of Ps done
    #pragma unroll
    for (int t = 0; t < 4; t++) {
        const int dc = wj * 32 + t * 8 + tg * 2;
        *(float2*)(sm + PS_OFF + (i0w + g8) * 68 + dc)     = make_float2(o[t][0], o[t][1]);
        *(float2*)(sm + PS_OFF + (i0w + g8 + 8) * 68 + dc) = make_float2(o[t][2], o[t][3]);
    }
    __syncthreads();

    {
        const int row = tid >> 2, qq = tid & 3;
        float ss = ssum_part;
        ss += __shfl_xor_sync(0xffffffffu, ss, 1);
        ss += __shfl_xor_sync(0xffffffffu, ss, 2);

        const int gi = bh * SS + i0 + row;
        const float mi   = g_m[gi];
        const float norm = fmaxf(fabsf(ss), __expf(-mi)) + 1e-6f;
        const float inv  = 1.0f / norm;

        const float4* orp = (const float4*)(sm + PS_OFF + row * 68 + qq * 16);
        float4 y0 = orp[0], y1 = orp[1], y2 = orp[2], y3 = orp[3];

        float sum = (((y0.x + y0.y) + (y0.z + y0.w))
                   + ((y1.x + y1.y) + (y1.z + y1.w)))
                  + (((y2.x + y2.y) + (y2.z + y2.w))
                   + ((y3.x + y3.y) + (y3.z + y3.w)));
        sum += __shfl_xor_sync(0xffffffffu, sum, 1);
        sum += __shfl_xor_sync(0xffffffffu, sum, 2);
        const float mu = sum * inv * (1.0f / 64.0f);

        float vals[16] = {y0.x, y0.y, y0.z, y0.w, y1.x, y1.y, y1.z, y1.w,
                          y2.x, y2.y, y2.z, y2.w, y3.x, y3.y, y3.z, y3.w};
        float var = 0.f;
        #pragma unroll
        for (int e = 0; e < 16; e++) {
            float dx = vals[e] * inv - mu;
            var += dx * dx;
        }
        var += __shfl_xor_sync(0xffffffffu, var, 1);
        var += __shfl_xor_sync(0xffffffffu, var, 2);
        const float sc = rsqrtf(var * (1.0f / 64.0f) + 1e-5f);

        float* op = out + (size_t)gi * 64 + qq * 16;
        #pragma unroll
        for (int e4 = 0; e4 < 4; e4++) {
            *(float4*)(op + e4 * 4) = make_float4(
                (vals[e4 * 4 + 0] * inv - mu) * sc,
                (vals[e4 * 4 + 1] * inv - mu) * sc,
                (vals[e4 * 4 + 2] * inv - mu) * sc,
                (vals[e4 * 4 + 3] * inv - mu) * sc);
        }
    }
}

// ---------------------------------------------------------------------------
extern "C" void kernel_launch(void* const* d_in, const int* in_sizes, int n_in,
                              void* d_out, int out_size) {
    const float* q  = (const float*)d_in[0];
    const float* k  = (const float*)d_in[1];
    const float* v  = (const float*)d_in[2];
    const float* Wi = (const float*)d_in[3];
    const float* bi = (const float*)d_in[4];
    const float* Wf = (const float*)d_in[5];
    const float* bf = (const float*)d_in[6];
    float* out = (float*)d_out;

    cudaFuncSetAttribute(attn_kernel,
                         cudaFuncAttributeMaxDynamicSharedMemorySize,
                         ATTN_SMEM_BYTES);

    gates_kernel<<<(BB * SS) / 8, 512>>>(q, k, v, Wi, bi, Wf, bf);
    scan_kernel<<<BH, 256>>>();
    attn_kernel<<<dim3(SS / 64, BH), 256, ATTN_SMEM_BYTES>>>(q, k, v, out);
}